// round 13
// baseline (speedup 1.0000x reference)
#include <cuda_runtime.h>
#include <math.h>

#define H 1024
#define L 4096
#define V 29
#define NB 148           // 1 block/SM, co-resident
#define NT 1024
#define WPB 32
#define WTOT (NB * WPB)  // 4736 warps

// ---------------- scratch (device globals) ----------------------------------
__device__ float g_scp[2 * L];         // score partials: [2*row+half]
__device__ float g_hh[4 * H];          // W_hh @ h0 full rows
__device__ float g_attn[H];
__device__ float g_xp[4 * H];          // combine partials: [4*row+q]
__device__ float g_gp[8 * H];          // W_ih partials: [2*row+half]
__device__ unsigned g_cnt = 0;
__device__ volatile unsigned g_flag = 0;

// ---------------- helpers ----------------------------------------------------
__device__ __forceinline__ float warp_sum(float v) {
#pragma unroll
    for (int o = 16; o; o >>= 1) v += __shfl_xor_sync(0xffffffffu, v, o);
    return v;
}
__device__ __forceinline__ float warp_max(float v) {
#pragma unroll
    for (int o = 16; o; o >>= 1) v = fmaxf(v, __shfl_xor_sync(0xffffffffu, v, o));
    return v;
}
__device__ __forceinline__ float sigmoidf_(float x) { return 1.0f / (1.0f + expf(-x)); }
__device__ __forceinline__ float dot4(float4 a, float4 b) {
    return a.x * b.x + a.y * b.y + a.z * b.z + a.w * b.w;
}

// L2 evict_last access policy (created once per thread)
__device__ __forceinline__ unsigned long long mk_policy() {
    unsigned long long p;
    asm("createpolicy.fractional.L2::evict_last.b64 %0, 1.0;" : "=l"(p));
    return p;
}
// read-only float4 load with evict_last cache hint
__device__ __forceinline__ float4 ldg_el(const float4* p, unsigned long long pol) {
    float4 v;
    asm("ld.global.nc.L2::cache_hint.v4.f32 {%0,%1,%2,%3}, [%4], %5;"
        : "=f"(v.x), "=f"(v.y), "=f"(v.z), "=f"(v.w) : "l"(p), "l"(pol));
    return v;
}

// 1024-elt dot: 8 float4 per lane, dual accumulators
__device__ __forceinline__ float dot_chunk8(const float4* __restrict__ w,
                                            const float4* __restrict__ v, int lane,
                                            unsigned long long pol) {
    float a0 = 0.f, a1 = 0.f;
#pragma unroll
    for (int k = 0; k < 8; k += 2) {
        a0 += dot4(ldg_el(&w[lane + 32 * k], pol),       v[lane + 32 * k]);
        a1 += dot4(ldg_el(&w[lane + 32 * (k + 1)], pol), v[lane + 32 * (k + 1)]);
    }
    return a0 + a1;
}
// 512-elt dot: 4 float4 per lane
__device__ __forceinline__ float dot_chunk4(const float4* __restrict__ w,
                                            const float4* __restrict__ v, int lane,
                                            unsigned long long pol) {
    float a0 = dot4(ldg_el(&w[lane], pol),      v[lane])
             + dot4(ldg_el(&w[lane + 64], pol), v[lane + 64]);
    float a1 = dot4(ldg_el(&w[lane + 32], pol), v[lane + 32])
             + dot4(ldg_el(&w[lane + 96], pol), v[lane + 96]);
    return a0 + a1;
}

__device__ __forceinline__ void grid_barrier(unsigned sense) {
    __syncthreads();
    if (threadIdx.x == 0) {
        __threadfence();
        unsigned old = atomicAdd(&g_cnt, 1u);
        if (old == NB - 1) {
            g_cnt = 0;
            __threadfence();
            g_flag = sense;
        } else {
            while (g_flag != sense) { __nanosleep(32); }
        }
        __threadfence();
    }
    __syncthreads();
}

// ---------------- the whole decoder step in one kernel -----------------------
__global__ void __launch_bounds__(NT, 1)
k_decoder(const int* __restrict__ tok,
          const float* __restrict__ h0,
          const float* __restrict__ c0,
          const float* __restrict__ enc,
          const float* __restrict__ emb,
          const float* __restrict__ attn_W,
          const float* __restrict__ attn_b,
          const float* __restrict__ comb_W,
          const float* __restrict__ comb_b,
          const float* __restrict__ W_ih,
          const float* __restrict__ W_hh,
          const float* __restrict__ b_ih,
          const float* __restrict__ b_hh,
          const float* __restrict__ out_W,
          const float* __restrict__ out_b,
          float* __restrict__ out) {
    __shared__ float s[2 * H];
    __shared__ float red[32];
    __shared__ float bcast;
    __shared__ float wts[28];
    __shared__ float z[32];

    const int t = threadIdx.x;
    const int warp = t >> 5, lane = t & 31;
    const int wg = blockIdx.x * WPB + warp;     // 0..4735
    float* attn_out = out + V + 2 * H;          // [lp | h | c | attn_w]
    const unsigned long long pol = mk_policy();

    // ===== Phase A: scores (8192 half-row chunks) + W_hh@h0 (4096 chunks) ===
    {
        const float* erow = emb + (size_t)tok[0] * H;
        s[t] = erow[t];
        s[H + t] = h0[t];
        if (blockIdx.x == 0) g_attn[t] = 0.0f;
        __syncthreads();

        const float4* sv = (const float4*)s;       // [emb | h0], 512 float4
#pragma unroll
        for (int c = wg; c < 3 * L; c += WTOT) {    // 12288 chunks
            if (c < 2 * L) {                        // score chunk
                int row = c >> 1, half = c & 1;
                const float4* w = (const float4*)(attn_W + (size_t)row * (2 * H) + half * H);
                float acc = dot_chunk8(w, sv + half * (H / 4), lane, pol);
                acc = warp_sum(acc);
                if (lane == 0) g_scp[c] = acc;
            } else {                                // hh chunk (full row)
                int row = c - 2 * L;
                const float4* w = (const float4*)(W_hh + (size_t)row * H);
                float acc = dot_chunk8(w, sv + (H / 4), lane, pol);
                acc = warp_sum(acc);
                if (lane == 0) g_hh[row] = acc;
            }
        }
    }
    grid_barrier(1);

    // ===== Phase B: softmax (redundant per-block reduce) + weighted enc sum =
    {
        const float2* sp = (const float2*)g_scp;    // pair = (half0, half1)
        float sc[4];
        float m = -1e30f;
#pragma unroll
        for (int k = 0; k < 4; k++) {
            float2 p = sp[t + k * 1024];
            sc[k] = p.x + p.y + attn_b[t + k * 1024];
            m = fmaxf(m, sc[k]);
        }
        m = warp_max(m);
        if (lane == 0) red[warp] = m;
        __syncthreads();
        if (warp == 0) {
            float x = red[lane];
            x = warp_max(x);
            if (lane == 0) bcast = x;
        }
        __syncthreads();
        const float M = bcast;

        float sum = 0.0f;
#pragma unroll
        for (int k = 0; k < 4; k++) sum += expf(sc[k] - M);
        sum = warp_sum(sum);
        __syncthreads();
        if (lane == 0) red[warp] = sum;
        __syncthreads();
        if (warp == 0) {
            float x = red[lane];
            x = warp_sum(x);
            if (lane == 0) bcast = x;
        }
        __syncthreads();
        const float invS = 1.0f / bcast;

        const int lb = blockIdx.x * 28;             // 28 enc rows per block
        const int nr = (lb < L) ? min(28, L - lb) : 0;
        if (t < nr) {
            float2 p = sp[lb + t];
            float w = expf(p.x + p.y + attn_b[lb + t] - M) * invS;
            wts[t] = w;
            attn_out[lb + t] = w;
        }
        __syncthreads();

        // float4 column ownership: grp handles rows grp, grp+4, ...
        if (nr > 0) {
            const int grp = t >> 8, col = t & 255;
            float4 acc = make_float4(0.f, 0.f, 0.f, 0.f);
            for (int r = grp; r < nr; r += 4) {
                const float4* ef = (const float4*)(enc + (size_t)(lb + r) * H);
                float4 v = ldg_el(&ef[col], pol);
                float w = wts[r];
                acc.x += w * v.x; acc.y += w * v.y; acc.z += w * v.z; acc.w += w * v.w;
            }
            float* dst = g_attn + 4 * col;
            atomicAdd(dst + 0, acc.x);
            atomicAdd(dst + 1, acc.y);
            atomicAdd(dst + 2, acc.z);
            atomicAdd(dst + 3, acc.w);
        }
    }
    grid_barrier(0);

    // ===== Phase C: x partials = comb_W @ [emb; attn] (4096 quarter chunks) =
    {
        s[H + t] = g_attn[t];              // emb still in s[0..H)
        __syncthreads();
        const float4* sv = (const float4*)s;
        if (wg < 4 * H) {                  // 4096 chunks of 512 elts
            int row = wg >> 2, q = wg & 3;
            const float4* w = (const float4*)(comb_W + (size_t)row * (2 * H) + q * 512);
            float acc = dot_chunk4(w, sv + q * 128, lane, pol);
            acc = warp_sum(acc);
            if (lane == 0) g_xp[wg] = acc;
        }
    }
    grid_barrier(1);

    // ===== Phase D: gate partials = W_ih @ x (8192 half-row chunks) =========
    {
        const float4* xp = (const float4*)g_xp;
        float4 p = xp[t];
        s[t] = fmaxf(p.x + p.y + p.z + p.w + comb_b[t], 0.0f);
        __syncthreads();

        const float4* sv = (const float4*)s;        // x, 256 float4
#pragma unroll
        for (int c = wg; c < 8 * H; c += WTOT) {    // 8192 chunks of 512
            int row = c >> 1, half = c & 1;
            const float4* w = (const float4*)(W_ih + (size_t)row * H + half * 512);
            float acc = dot_chunk4(w, sv + half * 128, lane, pol);
            acc = warp_sum(acc);
            if (lane == 0) g_gp[c] = acc;
        }
    }
    grid_barrier(0);

    // ===== Phase E: LSTM pointwise + out proj + log_softmax (block 0) =======
    if (blockIdx.x == 0) {
        const float2* gp = (const float2*)g_gp;
        float2 pi = gp[t];
        float2 pf = gp[H + t];
        float2 pg = gp[2 * H + t];
        float2 po = gp[3 * H + t];
        float ig = pi.x + pi.y + g_hh[t]         + b_ih[t]         + b_hh[t];
        float fg = pf.x + pf.y + g_hh[H + t]     + b_ih[H + t]     + b_hh[H + t];
        float gg = pg.x + pg.y + g_hh[2 * H + t] + b_ih[2 * H + t] + b_hh[2 * H + t];
        float og = po.x + po.y + g_hh[3 * H + t] + b_ih[3 * H + t] + b_hh[3 * H + t];
        float c = sigmoidf_(fg) * c0[t] + sigmoidf_(ig) * tanhf(gg);
        float h = sigmoidf_(og) * tanhf(c);
        out[V + t] = h;
        out[V + H + t] = c;
        s[t] = h;
        __syncthreads();

        if (warp < V) {
            const float4* wr = (const float4*)(out_W + (size_t)warp * H);
            const float4* hv = (const float4*)s;
            float acc = 0.0f;
#pragma unroll
            for (int k = lane; k < H / 4; k += 32) acc += dot4(ldg_el(&wr[k], pol), hv[k]);
            acc = warp_sum(acc);
            if (lane == 0) z[warp] = acc + out_b[warp];
        }
        __syncthreads();

        if (t == 0) {
            float m = -1e30f;
            for (int r = 0; r < V; r++) m = fmaxf(m, z[r]);
            float ssum = 0.0f;
            for (int r = 0; r < V; r++) ssum += expf(z[r] - m);
            float ls = m + logf(ssum);
            for (int r = 0; r < V; r++) out[r] = z[r] - ls;
        }
    }
}

// ---------------- launch ------------------------------------------------------
extern "C" void kernel_launch(void* const* d_in, const int* in_sizes, int n_in,
                              void* d_out, int out_size) {
    const int*   tok    = (const int*)  d_in[0];
    const float* h0     = (const float*)d_in[1];
    const float* c0     = (const float*)d_in[2];
    const float* enc    = (const float*)d_in[3];
    const float* emb    = (const float*)d_in[4];
    const float* attn_W = (const float*)d_in[5];
    const float* attn_b = (const float*)d_in[6];
    const float* comb_W = (const float*)d_in[7];
    const float* comb_b = (const float*)d_in[8];
    const float* W_ih   = (const float*)d_in[9];
    const float* W_hh   = (const float*)d_in[10];
    const float* b_ih   = (const float*)d_in[11];
    const float* b_hh   = (const float*)d_in[12];
    const float* out_W  = (const float*)d_in[13];
    const float* out_b  = (const float*)d_in[14];
    float* out = (float*)d_out;

    k_decoder<<<NB, NT>>>(tok, h0, c0, enc, emb, attn_W, attn_b,
                          comb_W, comb_b, W_ih, W_hh, b_ih, b_hh,
                          out_W, out_b, out);
}

// round 14
// speedup vs baseline: 1.0603x; 1.0603x over previous
#include <cuda_runtime.h>
#include <math.h>

#define H 1024
#define L 4096
#define V 29
#define NB 148           // 1 block/SM, co-resident
#define NT 1024
#define WPB 32
#define WTOT (NB * WPB)  // 4736 warps

// ---------------- scratch (device globals) ----------------------------------
__device__ float g_scp[2 * L];         // score partials: [2*row+half]
__device__ float g_hh[4 * H];          // W_hh @ h0 full rows
__device__ float g_attn[H];
__device__ float g_xp[4 * H];          // combine partials: [4*row+q]
__device__ float g_gp[8 * H];          // W_ih partials: [2*row+half]
__device__ unsigned g_tk[3];           // work-steal tickets (A, C, D)
__device__ unsigned g_cnt = 0;
__device__ volatile unsigned g_flag = 0;

// ---------------- helpers ----------------------------------------------------
__device__ __forceinline__ float warp_sum(float v) {
#pragma unroll
    for (int o = 16; o; o >>= 1) v += __shfl_xor_sync(0xffffffffu, v, o);
    return v;
}
__device__ __forceinline__ float warp_max(float v) {
#pragma unroll
    for (int o = 16; o; o >>= 1) v = fmaxf(v, __shfl_xor_sync(0xffffffffu, v, o));
    return v;
}
__device__ __forceinline__ float sigmoidf_(float x) { return 1.0f / (1.0f + expf(-x)); }
__device__ __forceinline__ float dot4(float4 a, float4 b) {
    return a.x * b.x + a.y * b.y + a.z * b.z + a.w * b.w;
}

// 1024-elt dot: 8 float4 per lane, dual accumulators (plain cached loads)
__device__ __forceinline__ float dot_chunk8(const float4* __restrict__ w,
                                            const float4* __restrict__ v, int lane) {
    float a0 = 0.f, a1 = 0.f;
#pragma unroll
    for (int k = 0; k < 8; k += 2) {
        a0 += dot4(w[lane + 32 * k],       v[lane + 32 * k]);
        a1 += dot4(w[lane + 32 * (k + 1)], v[lane + 32 * (k + 1)]);
    }
    return a0 + a1;
}
// 512-elt dot: 4 float4 per lane
__device__ __forceinline__ float dot_chunk4(const float4* __restrict__ w,
                                            const float4* __restrict__ v, int lane) {
    float a0 = dot4(w[lane],      v[lane])      + dot4(w[lane + 64], v[lane + 64]);
    float a1 = dot4(w[lane + 32], v[lane + 32]) + dot4(w[lane + 96], v[lane + 96]);
    return a0 + a1;
}

// grid barrier; leader optionally resets a ticket counter before release
__device__ __forceinline__ void grid_barrier(unsigned sense, int reset_tk) {
    __syncthreads();
    if (threadIdx.x == 0) {
        __threadfence();
        unsigned old = atomicAdd(&g_cnt, 1u);
        if (old == NB - 1) {
            g_cnt = 0;
            if (reset_tk >= 0) g_tk[reset_tk] = 0;
            __threadfence();
            g_flag = sense;
        } else {
            while (g_flag != sense) { __nanosleep(32); }
        }
        __threadfence();
    }
    __syncthreads();
}

// warp-level ticket grab (lane 0 does the atomic, broadcast to warp)
__device__ __forceinline__ unsigned grab(unsigned* tk, unsigned batch, int lane) {
    unsigned c;
    if (lane == 0) c = atomicAdd(tk, batch);
    return __shfl_sync(0xffffffffu, c, 0);
}

// ---------------- the whole decoder step in one kernel -----------------------
__global__ void __launch_bounds__(NT, 1)
k_decoder(const int* __restrict__ tok,
          const float* __restrict__ h0,
          const float* __restrict__ c0,
          const float* __restrict__ enc,
          const float* __restrict__ emb,
          const float* __restrict__ attn_W,
          const float* __restrict__ attn_b,
          const float* __restrict__ comb_W,
          const float* __restrict__ comb_b,
          const float* __restrict__ W_ih,
          const float* __restrict__ W_hh,
          const float* __restrict__ b_ih,
          const float* __restrict__ b_hh,
          const float* __restrict__ out_W,
          const float* __restrict__ out_b,
          float* __restrict__ out) {
    __shared__ float s[2 * H];
    __shared__ float red[32];
    __shared__ float bcast;
    __shared__ float wts[28];
    __shared__ float z[32];

    const int t = threadIdx.x;
    const int warp = t >> 5, lane = t & 31;
    float* attn_out = out + V + 2 * H;          // [lp | h | c | attn_w]

    // ===== Phase A: scores (8192 half-row chunks) + W_hh@h0 (4096 chunks) ===
    {
        const float* erow = emb + (size_t)tok[0] * H;
        s[t] = erow[t];
        s[H + t] = h0[t];
        if (blockIdx.x == 0) g_attn[t] = 0.0f;
        __syncthreads();

        const float4* sv = (const float4*)s;       // [emb | h0], 512 float4
        for (;;) {
            unsigned c0i = grab(&g_tk[0], 2, lane);  // 2 chunks per grab
            if (c0i >= 12288u) break;
            unsigned c1i = min(c0i + 2u, 12288u);
            for (unsigned c = c0i; c < c1i; c++) {
                if (c < 2 * L) {                     // score chunk
                    int row = c >> 1, half = c & 1;
                    const float4* w = (const float4*)(attn_W + (size_t)row * (2 * H) + half * H);
                    float acc = dot_chunk8(w, sv + half * (H / 4), lane);
                    acc = warp_sum(acc);
                    if (lane == 0) g_scp[c] = acc;
                } else {                             // hh chunk (full row)
                    int row = c - 2 * L;
                    const float4* w = (const float4*)(W_hh + (size_t)row * H);
                    float acc = dot_chunk8(w, sv + (H / 4), lane);
                    acc = warp_sum(acc);
                    if (lane == 0) g_hh[row] = acc;
                }
            }
        }
    }
    grid_barrier(1, 0);

    // ===== Phase B: softmax (redundant per-block reduce) + weighted enc sum =
    {
        const float2* sp = (const float2*)g_scp;    // pair = (half0, half1)
        float sc[4];
        float m = -1e30f;
#pragma unroll
        for (int k = 0; k < 4; k++) {
            float2 p = sp[t + k * 1024];
            sc[k] = p.x + p.y + attn_b[t + k * 1024];
            m = fmaxf(m, sc[k]);
        }
        m = warp_max(m);
        if (lane == 0) red[warp] = m;
        __syncthreads();
        if (warp == 0) {
            float x = red[lane];
            x = warp_max(x);
            if (lane == 0) bcast = x;
        }
        __syncthreads();
        const float M = bcast;

        float sum = 0.0f;
#pragma unroll
        for (int k = 0; k < 4; k++) sum += expf(sc[k] - M);
        sum = warp_sum(sum);
        __syncthreads();
        if (lane == 0) red[warp] = sum;
        __syncthreads();
        if (warp == 0) {
            float x = red[lane];
            x = warp_sum(x);
            if (lane == 0) bcast = x;
        }
        __syncthreads();
        const float invS = 1.0f / bcast;

        const int lb = blockIdx.x * 28;             // 28 enc rows per block
        const int nr = (lb < L) ? min(28, L - lb) : 0;
        if (t < nr) {
            float2 p = sp[lb + t];
            float w = expf(p.x + p.y + attn_b[lb + t] - M) * invS;
            wts[t] = w;
            attn_out[lb + t] = w;
        }
        __syncthreads();

        if (nr > 0) {
            float acc = 0.0f;
            const float* e = enc + (size_t)lb * H + t;
#pragma unroll 7
            for (int r = 0; r < nr; r++) acc += wts[r] * e[(size_t)r * H];
            atomicAdd(&g_attn[t], acc);
        }
    }
    grid_barrier(0, -1);

    // ===== Phase C: x partials = comb_W @ [emb; attn] (4096 quarter chunks) =
    {
        s[H + t] = g_attn[t];              // emb still in s[0..H)
        __syncthreads();
        const float4* sv = (const float4*)s;
        for (;;) {
            unsigned c = grab(&g_tk[1], 1, lane);
            if (c >= 4096u) break;
            int row = c >> 2, q = c & 3;
            const float4* w = (const float4*)(comb_W + (size_t)row * (2 * H) + q * 512);
            float acc = dot_chunk4(w, sv + q * 128, lane);
            acc = warp_sum(acc);
            if (lane == 0) g_xp[c] = acc;
        }
    }
    grid_barrier(1, 1);

    // ===== Phase D: gate partials = W_ih @ x (8192 half-row chunks) =========
    {
        const float4* xp = (const float4*)g_xp;
        float4 p = xp[t];
        s[t] = fmaxf(p.x + p.y + p.z + p.w + comb_b[t], 0.0f);
        __syncthreads();

        const float4* sv = (const float4*)s;        // x, 256 float4
        for (;;) {
            unsigned c0i = grab(&g_tk[2], 2, lane);
            if (c0i >= 8192u) break;
            unsigned c1i = min(c0i + 2u, 8192u);
            for (unsigned c = c0i; c < c1i; c++) {
                int row = c >> 1, half = c & 1;
                const float4* w = (const float4*)(W_ih + (size_t)row * H + half * 512);
                float acc = dot_chunk4(w, sv + half * 128, lane);
                acc = warp_sum(acc);
                if (lane == 0) g_gp[c] = acc;
            }
        }
    }
    grid_barrier(0, 2);

    // ===== Phase E: LSTM pointwise + out proj + log_softmax (block 0) =======
    if (blockIdx.x == 0) {
        const float2* gp = (const float2*)g_gp;
        float2 pi = gp[t];
        float2 pf = gp[H + t];
        float2 pg = gp[2 * H + t];
        float2 po = gp[3 * H + t];
        float ig = pi.x + pi.y + g_hh[t]         + b_ih[t]         + b_hh[t];
        float fg = pf.x + pf.y + g_hh[H + t]     + b_ih[H + t]     + b_hh[H + t];
        float gg = pg.x + pg.y + g_hh[2 * H + t] + b_ih[2 * H + t] + b_hh[2 * H + t];
        float og = po.x + po.y + g_hh[3 * H + t] + b_ih[3 * H + t] + b_hh[3 * H + t];
        float c = sigmoidf_(fg) * c0[t] + sigmoidf_(ig) * tanhf(gg);
        float h = sigmoidf_(og) * tanhf(c);
        out[V + t] = h;
        out[V + H + t] = c;
        s[t] = h;
        __syncthreads();

        if (warp < V) {
            const float4* wr = (const float4*)(out_W + (size_t)warp * H);
            const float4* hv = (const float4*)s;
            float acc = 0.0f;
#pragma unroll
            for (int k = lane; k < H / 4; k += 32) acc += dot4(wr[k], hv[k]);
            acc = warp_sum(acc);
            if (lane == 0) z[warp] = acc + out_b[warp];
        }
        __syncthreads();

        if (t == 0) {
            float m = -1e30f;
            for (int r = 0; r < V; r++) m = fmaxf(m, z[r]);
            float ssum = 0.0f;
            for (int r = 0; r < V; r++) ssum += expf(z[r] - m);
            float ls = m + logf(ssum);
            for (int r = 0; r < V; r++) out[r] = z[r] - ls;
        }
    }
}

// ---------------- launch ------------------------------------------------------
extern "C" void kernel_launch(void* const* d_in, const int* in_sizes, int n_in,
                              void* d_out, int out_size) {
    const int*   tok    = (const int*)  d_in[0];
    const float* h0     = (const float*)d_in[1];
    const float* c0     = (const float*)d_in[2];
    const float* enc    = (const float*)d_in[3];
    const float* emb    = (const float*)d_in[4];
    const float* attn_W = (const float*)d_in[5];
    const float* attn_b = (const float*)d_in[6];
    const float* comb_W = (const float*)d_in[7];
    const float* comb_b = (const float*)d_in[8];
    const float* W_ih   = (const float*)d_in[9];
    const float* W_hh   = (const float*)d_in[10];
    const float* b_ih   = (const float*)d_in[11];
    const float* b_hh   = (const float*)d_in[12];
    const float* out_W  = (const float*)d_in[13];
    const float* out_b  = (const float*)d_in[14];
    float* out = (float*)d_out;

    k_decoder<<<NB, NT>>>(tok, h0, c0, enc, emb, attn_W, attn_b,
                          comb_W, comb_b, W_ih, W_hh, b_ih, b_hh,
                          out_W, out_b, out);
}

// round 15
// speedup vs baseline: 1.3542x; 1.2772x over previous
#include <cuda_runtime.h>
#include <math.h>

#define H 1024
#define L 4096
#define V 29
#define NB 296           // 2 blocks/SM x 148 SMs, co-resident
#define NT 512
#define WPB 16
#define WTOT (NB * WPB)  // 4736 warps

// ---------------- scratch (device globals) ----------------------------------
__device__ float g_scp[2 * L];         // score partials: [2*row+half]
__device__ float g_hh[4 * H];          // W_hh @ h0 full rows
__device__ float g_attn[H];
__device__ float g_xp[4 * H];          // combine partials: [4*row+q]
__device__ float g_gp[8 * H];          // W_ih partials: [2*row+half]
__device__ unsigned g_cnt = 0;
__device__ volatile unsigned g_flag = 0;

// ---------------- helpers ----------------------------------------------------
__device__ __forceinline__ float warp_sum(float v) {
#pragma unroll
    for (int o = 16; o; o >>= 1) v += __shfl_xor_sync(0xffffffffu, v, o);
    return v;
}
__device__ __forceinline__ float warp_max(float v) {
#pragma unroll
    for (int o = 16; o; o >>= 1) v = fmaxf(v, __shfl_xor_sync(0xffffffffu, v, o));
    return v;
}
__device__ __forceinline__ float sigmoidf_(float x) { return 1.0f / (1.0f + expf(-x)); }
__device__ __forceinline__ float dot4(float4 a, float4 b) {
    return a.x * b.x + a.y * b.y + a.z * b.z + a.w * b.w;
}

// 1024-elt dot: ALL 8 float4 loads batched into registers before any FMA
__device__ __forceinline__ float dot_chunk8(const float4* __restrict__ w,
                                            const float4* __restrict__ v, int lane) {
    float4 wr[8];
#pragma unroll
    for (int k = 0; k < 8; k++) wr[k] = w[lane + 32 * k];
    float a0 = 0.f, a1 = 0.f;
#pragma unroll
    for (int k = 0; k < 8; k += 2) {
        a0 += dot4(wr[k],     v[lane + 32 * k]);
        a1 += dot4(wr[k + 1], v[lane + 32 * (k + 1)]);
    }
    return a0 + a1;
}
// 512-elt dot: 4 batched float4 loads
__device__ __forceinline__ float dot_chunk4(const float4* __restrict__ w,
                                            const float4* __restrict__ v, int lane) {
    float4 wr[4];
#pragma unroll
    for (int k = 0; k < 4; k++) wr[k] = w[lane + 32 * k];
    float a0 = dot4(wr[0], v[lane])      + dot4(wr[2], v[lane + 64]);
    float a1 = dot4(wr[1], v[lane + 32]) + dot4(wr[3], v[lane + 96]);
    return a0 + a1;
}

__device__ __forceinline__ void grid_barrier(unsigned sense) {
    __syncthreads();
    if (threadIdx.x == 0) {
        __threadfence();
        unsigned old = atomicAdd(&g_cnt, 1u);
        if (old == NB - 1) {
            g_cnt = 0;
            __threadfence();
            g_flag = sense;
        } else {
            while (g_flag != sense) { __nanosleep(32); }
        }
        __threadfence();
    }
    __syncthreads();
}

// ---------------- the whole decoder step in one kernel -----------------------
__global__ void __launch_bounds__(NT, 2)
k_decoder(const int* __restrict__ tok,
          const float* __restrict__ h0,
          const float* __restrict__ c0,
          const float* __restrict__ enc,
          const float* __restrict__ emb,
          const float* __restrict__ attn_W,
          const float* __restrict__ attn_b,
          const float* __restrict__ comb_W,
          const float* __restrict__ comb_b,
          const float* __restrict__ W_ih,
          const float* __restrict__ W_hh,
          const float* __restrict__ b_ih,
          const float* __restrict__ b_hh,
          const float* __restrict__ out_W,
          const float* __restrict__ out_b,
          float* __restrict__ out) {
    __shared__ float s[2 * H];
    __shared__ float red[16];
    __shared__ float bcast;
    __shared__ float wts[14];
    __shared__ float z[32];

    const int t = threadIdx.x;
    const int warp = t >> 5, lane = t & 31;
    const int b = blockIdx.x;
    const int wg = b * WPB + warp;              // 0..4735
    float* attn_out = out + V + 2 * H;          // [lp | h | c | attn_w]

    // ===== Phase A: scores (8192 half-row chunks) + W_hh@h0 (4096 chunks) ===
    {
        const float* erow = emb + (size_t)tok[0] * H;
        s[t] = erow[t];
        s[t + 512] = erow[t + 512];
        s[H + t] = h0[t];
        s[H + t + 512] = h0[t + 512];
        if (b == 0) { g_attn[t] = 0.0f; g_attn[t + 512] = 0.0f; }
        __syncthreads();

        const float4* sv = (const float4*)s;       // [emb | h0], 512 float4
#pragma unroll
        for (int c = wg; c < 3 * L; c += WTOT) {    // 12288 chunks
            if (c < 2 * L) {                        // score chunk
                int row = c >> 1, half = c & 1;
                const float4* w = (const float4*)(attn_W + (size_t)row * (2 * H) + half * H);
                float acc = dot_chunk8(w, sv + half * (H / 4), lane);
                acc = warp_sum(acc);
                if (lane == 0) g_scp[c] = acc;
            } else {                                // hh chunk (full row)
                int row = c - 2 * L;
                const float4* w = (const float4*)(W_hh + (size_t)row * H);
                float acc = dot_chunk8(w, sv + (H / 4), lane);
                acc = warp_sum(acc);
                if (lane == 0) g_hh[row] = acc;
            }
        }
    }
    grid_barrier(1);

    // ===== Phase B: softmax (redundant per-block reduce) + weighted enc sum =
    {
        const float2* sp = (const float2*)g_scp;    // pair = (half0, half1)
        float sc[8];
        float m = -1e30f;
#pragma unroll
        for (int k = 0; k < 8; k++) {
            float2 p = sp[t + k * 512];
            sc[k] = p.x + p.y + attn_b[t + k * 512];
            m = fmaxf(m, sc[k]);
        }
        m = warp_max(m);
        if (lane == 0) red[warp] = m;
        __syncthreads();
        if (warp == 0) {
            float x = (lane < 16) ? red[lane] : -1e30f;
            x = warp_max(x);
            if (lane == 0) bcast = x;
        }
        __syncthreads();
        const float M = bcast;

        float sum = 0.0f;
#pragma unroll
        for (int k = 0; k < 8; k++) sum += expf(sc[k] - M);
        sum = warp_sum(sum);
        __syncthreads();
        if (lane == 0) red[warp] = sum;
        __syncthreads();
        if (warp == 0) {
            float x = (lane < 16) ? red[lane] : 0.0f;
            x = warp_sum(x);
            if (lane == 0) bcast = x;
        }
        __syncthreads();
        const float invS = 1.0f / bcast;

        const int lb = b * 14;                      // 14 enc rows per block
        const int nr = (lb < L) ? min(14, L - lb) : 0;
        if (t < nr) {
            float2 p = sp[lb + t];
            float w = expf(p.x + p.y + attn_b[lb + t] - M) * invS;
            wts[t] = w;
            attn_out[lb + t] = w;
        }
        __syncthreads();

        if (nr > 0) {
            // thread t owns float2 column pair t (512*2 = 1024 = H)
            const float2* ef = (const float2*)(enc + (size_t)lb * H) + t;
            float2 acc = make_float2(0.f, 0.f);
#pragma unroll 7
            for (int r = 0; r < nr; r++) {
                float2 v = ef[(size_t)r * (H / 2)];
                float w = wts[r];
                acc.x += w * v.x;
                acc.y += w * v.y;
            }
            atomicAdd(&g_attn[2 * t],     acc.x);
            atomicAdd(&g_attn[2 * t + 1], acc.y);
        }
    }
    grid_barrier(0);

    // ===== Phase C: x partials = comb_W @ [emb; attn] (4096 quarter chunks) =
    {
        s[H + t] = g_attn[t];              // emb still in s[0..H)
        s[H + t + 512] = g_attn[t + 512];
        __syncthreads();
        const float4* sv = (const float4*)s;
        if (wg < 4 * H) {                  // 4096 chunks of 512 elts
            int row = wg >> 2, q = wg & 3;
            const float4* w = (const float4*)(comb_W + (size_t)row * (2 * H) + q * 512);
            float acc = dot_chunk4(w, sv + q * 128, lane);
            acc = warp_sum(acc);
            if (lane == 0) g_xp[wg] = acc;
        }
    }
    grid_barrier(1);

    // ===== Phase D: gate partials = W_ih @ x (8192 half-row chunks) =========
    {
        const float4* xp = (const float4*)g_xp;
#pragma unroll
        for (int k = 0; k < 2; k++) {
            int i = t + k * 512;
            float4 p = xp[i];
            s[i] = fmaxf(p.x + p.y + p.z + p.w + comb_b[i], 0.0f);
        }
        __syncthreads();

        const float4* sv = (const float4*)s;        // x, 256 float4
#pragma unroll
        for (int c = wg; c < 8 * H; c += WTOT) {    // 8192 chunks of 512
            int row = c >> 1, half = c & 1;
            const float4* w = (const float4*)(W_ih + (size_t)row * H + half * 512);
            float acc = dot_chunk4(w, sv + half * 128, lane);
            acc = warp_sum(acc);
            if (lane == 0) g_gp[c] = acc;
        }
    }
    grid_barrier(0);

    // ===== Phase E: LSTM pointwise + out proj + log_softmax (block 0) =======
    if (b == 0) {
        const float2* gp = (const float2*)g_gp;
#pragma unroll
        for (int k = 0; k < 2; k++) {
            int i = t + k * 512;
            float2 pi = gp[i];
            float2 pf = gp[H + i];
            float2 pg = gp[2 * H + i];
            float2 po = gp[3 * H + i];
            float ig = pi.x + pi.y + g_hh[i]         + b_ih[i]         + b_hh[i];
            float fg = pf.x + pf.y + g_hh[H + i]     + b_ih[H + i]     + b_hh[H + i];
            float gg = pg.x + pg.y + g_hh[2 * H + i] + b_ih[2 * H + i] + b_hh[2 * H + i];
            float og = po.x + po.y + g_hh[3 * H + i] + b_ih[3 * H + i] + b_hh[3 * H + i];
            float c = sigmoidf_(fg) * c0[i] + sigmoidf_(ig) * tanhf(gg);
            float h = sigmoidf_(og) * tanhf(c);
            out[V + i] = h;
            out[V + H + i] = c;
            s[i] = h;
        }
        __syncthreads();

        const float4* hv = (const float4*)s;
        for (int row = warp; row < V; row += WPB) {
            const float4* wr = (const float4*)(out_W + (size_t)row * H);
            float acc = 0.0f;
#pragma unroll
            for (int k = lane; k < H / 4; k += 32) acc += dot4(wr[k], hv[k]);
            acc = warp_sum(acc);
            if (lane == 0) z[row] = acc + out_b[row];
        }
        __syncthreads();

        if (t == 0) {
            float m = -1e30f;
            for (int r = 0; r < V; r++) m = fmaxf(m, z[r]);
            float ssum = 0.0f;
            for (int r = 0; r < V; r++) ssum += expf(z[r] - m);
            float ls = m + logf(ssum);
            for (int r = 0; r < V; r++) out[r] = z[r] - ls;
        }
    }
}

// ---------------- launch ------------------------------------------------------
extern "C" void kernel_launch(void* const* d_in, const int* in_sizes, int n_in,
                              void* d_out, int out_size) {
    const int*   tok    = (const int*)  d_in[0];
    const float* h0     = (const float*)d_in[1];
    const float* c0     = (const float*)d_in[2];
    const float* enc    = (const float*)d_in[3];
    const float* emb    = (const float*)d_in[4];
    const float* attn_W = (const float*)d_in[5];
    const float* attn_b = (const float*)d_in[6];
    const float* comb_W = (const float*)d_in[7];
    const float* comb_b = (const float*)d_in[8];
    const float* W_ih   = (const float*)d_in[9];
    const float* W_hh   = (const float*)d_in[10];
    const float* b_ih   = (const float*)d_in[11];
    const float* b_hh   = (const float*)d_in[12];
    const float* out_W  = (const float*)d_in[13];
    const float* out_b  = (const float*)d_in[14];
    float* out = (float*)d_out;

    k_decoder<<<NB, NT>>>(tok, h0, c0, enc, emb, attn_W, attn_b,
                          comb_W, comb_b, W_ih, W_hh, b_ih, b_hh,
                          out_W, out_b, out);
}

// round 16
// speedup vs baseline: 1.7066x; 1.2603x over previous
#include <cuda_runtime.h>
#include <math.h>

#define H 1024
#define L 4096
#define V 29
#define NB 128           // blocks (<= SM count, 1 block/SM -> co-resident)
#define NT 1024          // threads per block
#define WPB 32           // warps per block

// ---------------- scratch (device globals) ----------------------------------
__device__ float g_scores[L];
__device__ float g_hh[4 * H];          // W_hh @ h0 partial gates
__device__ float g_attn_applied[H];
__device__ float g_x[H];
__device__ float g_gates[4 * H];
__device__ unsigned g_cnt = 0;
__device__ volatile unsigned g_flag = 0;

// ---------------- helpers ----------------------------------------------------
__device__ __forceinline__ float warp_sum(float v) {
#pragma unroll
    for (int o = 16; o; o >>= 1) v += __shfl_xor_sync(0xffffffffu, v, o);
    return v;
}
__device__ __forceinline__ float warp_max(float v) {
#pragma unroll
    for (int o = 16; o; o >>= 1) v = fmaxf(v, __shfl_xor_sync(0xffffffffu, v, o));
    return v;
}
__device__ __forceinline__ float sigmoidf_(float x) { return 1.0f / (1.0f + expf(-x)); }

// sense-reversing grid barrier. Requires all NB blocks co-resident.
// Counter self-resets; flag returns to 0 at kernel end (EVEN # of barriers).
__device__ __forceinline__ void grid_barrier(unsigned sense) {
    __syncthreads();
    if (threadIdx.x == 0) {
        __threadfence();
        unsigned old = atomicAdd(&g_cnt, 1u);
        if (old == NB - 1) {
            g_cnt = 0;
            __threadfence();
            g_flag = sense;
        } else {
            while (g_flag != sense) { __nanosleep(64); }
        }
        __threadfence();
    }
    __syncthreads();
}

__device__ __forceinline__ float dot4(float4 a, float4 b) {
    return a.x * b.x + a.y * b.y + a.z * b.z + a.w * b.w;
}

// ---------------- the whole decoder step in one kernel -----------------------
__global__ void __launch_bounds__(NT, 1)
k_decoder(const int* __restrict__ tok,
          const float* __restrict__ h0,
          const float* __restrict__ c0,
          const float* __restrict__ enc,
          const float* __restrict__ emb,
          const float* __restrict__ attn_W,
          const float* __restrict__ attn_b,
          const float* __restrict__ comb_W,
          const float* __restrict__ comb_b,
          const float* __restrict__ W_ih,
          const float* __restrict__ W_hh,
          const float* __restrict__ b_ih,
          const float* __restrict__ b_hh,
          const float* __restrict__ out_W,
          const float* __restrict__ out_b,
          float* __restrict__ out) {
    __shared__ float s[2 * H];
    __shared__ float red[32];
    __shared__ float bcast;
    __shared__ float wts[32];
    __shared__ float z[32];

    const int t = threadIdx.x;          // 0..1023
    const int warp = t >> 5, lane = t & 31;
    float* attn_out = out + V + 2 * H;  // d_out layout: [lp | h | c | attn_w]

    // ============ Phase A: attn scores + W_hh@h0 (independent, fused) =======
    {
        const float* erow = emb + (size_t)tok[0] * H;
        s[t] = erow[t];
        s[H + t] = h0[t];
        if (blockIdx.x == 0) g_attn_applied[t] = 0.0f;
        __syncthreads();

        int gw = blockIdx.x * WPB + warp;   // 0..4095

        // scores row gw: dot over 2H (dual accumulators)
        {
            const float4* w = (const float4*)(attn_W + (size_t)gw * (2 * H));
            const float4* c = (const float4*)s;
            float a0 = 0.0f, a1 = 0.0f;
#pragma unroll 4
            for (int j = lane; j < (2 * H) / 4; j += 64) {
                a0 += dot4(w[j], c[j]);
                a1 += dot4(w[j + 32], c[j + 32]);
            }
            float acc = warp_sum(a0 + a1);
            if (lane == 0) g_scores[gw] = acc + attn_b[gw];
        }
        // hh row gw: dot over H
        {
            const float4* w = (const float4*)(W_hh + (size_t)gw * H);
            const float4* c = (const float4*)(s + H);
            float a0 = 0.0f, a1 = 0.0f;
#pragma unroll 2
            for (int j = lane; j < H / 4; j += 64) {
                a0 += dot4(w[j], c[j]);
                a1 += dot4(w[j + 32], c[j + 32]);
            }
            float acc = warp_sum(a0 + a1);
            if (lane == 0) g_hh[gw] = acc;
        }
    }
    grid_barrier(1);

    // ============ Phase B: softmax (redundant per-block) + weighted enc sum ==
    {
        float sc[4];
        float m = -1e30f;
#pragma unroll
        for (int k = 0; k < 4; k++) {
            sc[k] = g_scores[t + k * 1024];
            m = fmaxf(m, sc[k]);
        }
        m = warp_max(m);
        if (lane == 0) red[warp] = m;
        __syncthreads();
        if (warp == 0) {
            float x = red[lane];
            x = warp_max(x);
            if (lane == 0) bcast = x;
        }
        __syncthreads();
        const float M = bcast;

        float sum = 0.0f;
#pragma unroll
        for (int k = 0; k < 4; k++) sum += expf(sc[k] - M);
        sum = warp_sum(sum);
        __syncthreads();
        if (lane == 0) red[warp] = sum;
        __syncthreads();
        if (warp == 0) {
            float x = red[lane];
            x = warp_sum(x);
            if (lane == 0) bcast = x;
        }
        __syncthreads();
        const float invS = 1.0f / bcast;

        const int lb = blockIdx.x * 32;    // this block's 32 encoder rows
        if (t < 32) {
            float w = expf(g_scores[lb + t] - M) * invS;
            wts[t] = w;
            attn_out[lb + t] = w;
        }
        __syncthreads();

        // thread t owns column t (1024 threads = H columns), fully coalesced
        float acc = 0.0f;
        const float* e = enc + (size_t)lb * H + t;
#pragma unroll 8
        for (int r = 0; r < 32; r++) acc += wts[r] * e[(size_t)r * H];
        atomicAdd(&g_attn_applied[t], acc);
    }
    grid_barrier(0);

    // ============ Phase C: x = relu(comb_W @ [emb; attn_applied] + b) =======
    {
        s[H + t] = g_attn_applied[t];      // emb still resident in s[0..H)
        __syncthreads();

        int row = blockIdx.x * 8 + (warp >> 2);   // 8 rows/block, 4 warps/row
        int part = warp & 3;
        const float4* w = (const float4*)(comb_W + (size_t)row * (2 * H));
        const float4* c = (const float4*)s;
        float acc = 0.0f;
        int j0 = part * 128 + lane;
#pragma unroll
        for (int j = j0; j < part * 128 + 128; j += 32) acc += dot4(w[j], c[j]);
        acc = warp_sum(acc);
        if (lane == 0) red[warp] = acc;
        __syncthreads();
        if (warp == 0 && lane < 8) {
            int r2 = blockIdx.x * 8 + lane;
            float v = red[lane * 4] + red[lane * 4 + 1] +
                      red[lane * 4 + 2] + red[lane * 4 + 3];
            g_x[r2] = fmaxf(v + comb_b[r2], 0.0f);
        }
    }
    grid_barrier(1);

    // ============ Phase D: gates = W_ih@x + hh + b_ih + b_hh ================
    {
        s[t] = g_x[t];
        __syncthreads();

        int row = blockIdx.x * 32 + warp;  // 4096 rows over 128 blocks
        const float4* w = (const float4*)(W_ih + (size_t)row * H);
        const float4* c = (const float4*)s;
        float a0 = 0.0f, a1 = 0.0f;
#pragma unroll 2
        for (int j = lane; j < H / 4; j += 64) {
            a0 += dot4(w[j], c[j]);
            a1 += dot4(w[j + 32], c[j + 32]);
        }
        float acc = warp_sum(a0 + a1);
        if (lane == 0)
            g_gates[row] = acc + g_hh[row] + b_ih[row] + b_hh[row];
    }
    grid_barrier(0);

    // ============ Phase E: LSTM pointwise + out proj + log_softmax =========
    if (blockIdx.x == 0) {
        float ig = g_gates[t];
        float fg = g_gates[H + t];
        float gg = g_gates[2 * H + t];
        float og = g_gates[3 * H + t];
        float c = sigmoidf_(fg) * c0[t] + sigmoidf_(ig) * tanhf(gg);
        float h = sigmoidf_(og) * tanhf(c);
        out[V + t] = h;
        out[V + H + t] = c;
        s[t] = h;
        __syncthreads();

        if (warp < V) {
            const float4* wr = (const float4*)(out_W + (size_t)warp * H);
            const float4* hv = (const float4*)s;
            float acc = 0.0f;
#pragma unroll
            for (int k = lane; k < H / 4; k += 32) acc += dot4(wr[k], hv[k]);
            acc = warp_sum(acc);
            if (lane == 0) z[warp] = acc + out_b[warp];
        }
        __syncthreads();

        // warp-parallel log_softmax over V=29 (replaces serial t==0 loop)
        if (warp == 0) {
            float v = (lane < V) ? z[lane] : -1e30f;
            float m = warp_max(v);
            float e = (lane < V) ? expf(v - m) : 0.0f;
            float ssum = warp_sum(e);
            float ls = m + logf(ssum);
            if (lane < V) out[lane] = v - ls;
        }
    }
}

// ---------------- launch ------------------------------------------------------
extern "C" void kernel_launch(void* const* d_in, const int* in_sizes, int n_in,
                              void* d_out, int out_size) {
    const int*   tok    = (const int*)  d_in[0];
    const float* h0     = (const float*)d_in[1];
    const float* c0     = (const float*)d_in[2];
    const float* enc    = (const float*)d_in[3];
    const float* emb    = (const float*)d_in[4];
    const float* attn_W = (const float*)d_in[5];
    const float* attn_b = (const float*)d_in[6];
    const float* comb_W = (const float*)d_in[7];
    const float* comb_b = (const float*)d_in[8];
    const float* W_ih   = (const float*)d_in[9];
    const float* W_hh   = (const float*)d_in[10];
    const float* b_ih   = (const float*)d_in[11];
    const float* b_hh   = (const float*)d_in[12];
    const float* out_W  = (const float*)d_in[13];
    const float* out_b  = (const float*)d_in[14];
    float* out = (float*)d_out;

    k_decoder<<<NB, NT>>>(tok, h0, c0, enc, emb, attn_W, attn_b,
                          comb_W, comb_b, W_ih, W_hh, b_ih, b_hh,
                          out_W, out_b, out);
}